// round 16
// baseline (speedup 1.0000x reference)
#include <cuda_runtime.h>
#include <cstdint>
#include <cstdio>

// Problem dims (fixed)
#define NROWS 8192
#define VDIM  2048
#define MDIM  128
#define HDIM  512

// Scratch (allocation-free rule: __device__ globals)
__device__ __align__(256) float g_feats [NROWS * MDIM];     // 4 MB
__device__ __align__(256) float g_h     [NROWS * HDIM];     // 16 MB (tf32-rounded)
__device__ __align__(256) float g_feats2[NROWS * MDIM];     // 4 MB (tf32-rounded)
__device__ __align__(256) float g_wmapT [VDIM * MDIM];      // 1 MB (tf32-rounded)
__device__ __align__(256) float g_w2r   [MDIM * MDIM * HDIM]; // 64 MB (tf32 W2)
__device__ __align__(256) float g_w1r   [4 * MDIM * MDIM];  // 256 KB (tf32 W1)
__device__ __align__(256) float g_wmh   [MDIM * VDIM];      // 1 MB (Wmap hi)
__device__ __align__(256) float g_wml   [MDIM * VDIM];      // 1 MB (Wmap lo)

// ---------------- common PTX helpers ----------------
__device__ __forceinline__ uint32_t smem_u32(const void* p) {
    uint32_t a;
    asm("{ .reg .u64 t; cvta.to.shared.u64 t, %1; cvt.u32.u64 %0, t; }"
        : "=r"(a) : "l"(p));
    return a;
}
__device__ __forceinline__ void cp_async16(uint32_t dst, const void* src) {
    asm volatile("cp.async.cg.shared.global [%0], [%1], 16;"
                 :: "r"(dst), "l"(src));
}
__device__ __forceinline__ void cp_commit() {
    asm volatile("cp.async.commit_group;" ::: "memory");
}
template <int N>
__device__ __forceinline__ void cp_wait() {
    asm volatile("cp.async.wait_group %0;" :: "n"(N) : "memory");
}
__device__ __forceinline__ uint32_t f2tf32(float f) {
    uint32_t r;
    asm("cvt.rna.tf32.f32 %0, %1;" : "=r"(r) : "f"(f));
    return r;
}
__device__ __forceinline__ void mma_tf32(float* d, const uint32_t* a,
                                         const uint32_t* b) {
    asm volatile(
        "mma.sync.aligned.m16n8k8.row.col.f32.tf32.tf32.f32 "
        "{%0,%1,%2,%3}, {%4,%5,%6,%7}, {%8,%9}, {%0,%1,%2,%3};"
        : "+f"(d[0]), "+f"(d[1]), "+f"(d[2]), "+f"(d[3])
        : "r"(a[0]), "r"(a[1]), "r"(a[2]), "r"(a[3]), "r"(b[0]), "r"(b[1]));
}
__device__ __forceinline__ void ldsm_x4(uint32_t& r0, uint32_t& r1,
                                        uint32_t& r2, uint32_t& r3,
                                        uint32_t addr) {
    asm volatile("ldmatrix.sync.aligned.m8n8.x4.shared.b16 {%0,%1,%2,%3}, [%4];"
                 : "=r"(r0), "=r"(r1), "=r"(r2), "=r"(r3) : "r"(addr));
}

// =======================================================================
// Pre-round a buffer to tf32 format
// =======================================================================
__global__ __launch_bounds__(256)
void round_tf32_kernel(const float4* __restrict__ in, float4* __restrict__ out,
                       int n4)
{
    int i = blockIdx.x * blockDim.x + threadIdx.x;
    int stride = gridDim.x * blockDim.x;
    for (; i < n4; i += stride) {
        float4 v = in[i];
        float4 o;
        o.x = __uint_as_float(f2tf32(v.x));
        o.y = __uint_as_float(f2tf32(v.y));
        o.z = __uint_as_float(f2tf32(v.z));
        o.w = __uint_as_float(f2tf32(v.w));
        out[i] = o;
    }
}

// =======================================================================
// 3xTF32 split (W_map only): hi = rnd(v), lo = rnd(v - hi)
// =======================================================================
__global__ __launch_bounds__(256)
void split_tf32_kernel(const float4* __restrict__ in,
                       float4* __restrict__ hi, float4* __restrict__ lo,
                       int n4)
{
    int i = blockIdx.x * blockDim.x + threadIdx.x;
    int stride = gridDim.x * blockDim.x;
    for (; i < n4; i += stride) {
        float4 v = in[i];
        float4 h4, l4;
        h4.x = __uint_as_float(f2tf32(v.x)); l4.x = __uint_as_float(f2tf32(v.x - h4.x));
        h4.y = __uint_as_float(f2tf32(v.y)); l4.y = __uint_as_float(f2tf32(v.y - h4.y));
        h4.z = __uint_as_float(f2tf32(v.z)); l4.z = __uint_as_float(f2tf32(v.z - h4.z));
        h4.w = __uint_as_float(f2tf32(v.w)); l4.w = __uint_as_float(f2tf32(v.w - h4.w));
        hi[i] = h4;
        lo[i] = l4;
    }
}

// =======================================================================
// W_map transpose (+ tf32 round): WT[v][i] = round(W[i][v])
// =======================================================================
__global__ __launch_bounds__(256)
void transpose_wmap(const float* __restrict__ W, float* __restrict__ WT)
{
    __shared__ float t[32][33];
    const int bx = blockIdx.x * 32;   // v
    const int by = blockIdx.y * 32;   // i
    const int tx = threadIdx.x & 31;
    const int ty = threadIdx.x >> 5;  // 0..7
#pragma unroll
    for (int r = 0; r < 32; r += 8)
        t[ty + r][tx] = W[(size_t)(by + ty + r) * VDIM + bx + tx];
    __syncthreads();
#pragma unroll
    for (int r = 0; r < 32; r += 8)
        WT[(size_t)(bx + ty + r) * MDIM + by + tx] =
            __uint_as_float(f2tf32(t[tx][ty + r]));
}

// =======================================================================
// Step 1 via 3xTF32, v2: BM=32, KC=32, 2 CTAs/SM.
//   feats = x @ Wmap^T;  xhi/xlo derived in registers from raw x fragments.
// Stage rows: x raw [0,32), Bhi [32,160), Blo [160,288), stride 36.
// smem 288*36*4*2 = 82944 B -> 2 CTAs/SM; grid 256.
// =======================================================================
#define G3_KC    32
#define G3_NCH   (VDIM / G3_KC)            // 64
#define G3_STR   36
#define G3_STAGE (288 * G3_STR)            // 10368 floats
#define G3_SMEM  (2 * G3_STAGE * 4)        // 82944 B

__global__ __launch_bounds__(256, 2)
void gemm_3xtf32(const float* __restrict__ x,
                 const float* __restrict__ wmh, const float* __restrict__ wml,
                 float* __restrict__ C)
{
    extern __shared__ float smf[];
    const uint32_t s_u = smem_u32(smf);

    const int tid  = threadIdx.x;
    const int wid  = tid >> 5;
    const int lane = tid & 31;
    const int wr   = wid >> 2;         // 0..1 -> rows 16*wr
    const int wc   = wid & 3;          // 0..3 -> cols 32*wc
    const int qr   = lane >> 2;
    const int qc   = lane & 3;
    const int m0   = blockIdx.x * 32;

    const int lt = lane >> 3;
    const int lr = lane & 7;
    const int a_off = (wr * 16 + (lt & 1) * 8 + lr) * G3_STR + (lt >> 1) * 4;
    const int b_off = (wc * 32 + (lt >> 1) * 8 + lr) * G3_STR + (lt & 1) * 4;

    float acc[4][4];                   // mt=1, nt=4 -> 16 regs
#pragma unroll
    for (int nt = 0; nt < 4; nt++)
#pragma unroll
        for (int v = 0; v < 4; v++) acc[nt][v] = 0.f;

    auto load_chunk = [&](int c) {
        const int s = c & 1;
        const int kc = c * G3_KC;
        const uint32_t base = s_u + s * G3_STAGE * 4;
        {   // x raw: 32 rows x 8 granules = 256 tasks (1 iter)
            int row = tid >> 3, g = tid & 7;
            cp_async16(base + (row * G3_STR + g * 4) * 4,
                       x + (size_t)(m0 + row) * VDIM + kc + g * 4);
        }
#pragma unroll
        for (int o = 0; o < 4; o++) {      // B hi: 128 rows x 8 granules
            int li = o * 256 + tid;
            int row = li >> 3, g = li & 7;
            cp_async16(base + ((32 + row) * G3_STR + g * 4) * 4,
                       wmh + (size_t)row * VDIM + kc + g * 4);
        }
#pragma unroll
        for (int o = 0; o < 4; o++) {      // B lo
            int li = o * 256 + tid;
            int row = li >> 3, g = li & 7;
            cp_async16(base + ((160 + row) * G3_STR + g * 4) * 4,
                       wml + (size_t)row * VDIM + kc + g * 4);
        }
        cp_commit();
    };

    load_chunk(0);

    for (int c = 0; c < G3_NCH; c++) {
        cp_wait<0>();
        __syncthreads();
        if (c + 1 < G3_NCH) load_chunk(c + 1);

        const uint32_t base = s_u + (c & 1) * G3_STAGE * 4;
        const uint32_t axo = base + (uint32_t)a_off * 4;
        const uint32_t bho = base + 32u * G3_STR * 4 + (uint32_t)b_off * 4;
        const uint32_t blo_ = base + 160u * G3_STR * 4 + (uint32_t)b_off * 4;

#pragma unroll
        for (int k8 = 0; k8 < 4; k8++) {
            const int k0 = k8 * 8;
            uint32_t ah[4], al[4], bh[4][2], bl[4][2];
            {
                uint32_t ar[4];
                ldsm_x4(ar[0], ar[1], ar[2], ar[3],
                        axo + (uint32_t)k0 * 4);
#pragma unroll
                for (int e = 0; e < 4; e++) {
                    float f  = __uint_as_float(ar[e]);
                    uint32_t hb = f2tf32(f);
                    ah[e] = hb;
                    al[e] = f2tf32(f - __uint_as_float(hb));
                }
            }
#pragma unroll
            for (int p = 0; p < 2; p++) {
                uint32_t r0, r1, r2, r3;
                ldsm_x4(r0, r1, r2, r3,
                        bho + (uint32_t)(p * 16 * G3_STR + k0) * 4);
                bh[2 * p][0] = r0;  bh[2 * p][1] = r1;
                bh[2 * p + 1][0] = r2;  bh[2 * p + 1][1] = r3;
                ldsm_x4(r0, r1, r2, r3,
                        blo_ + (uint32_t)(p * 16 * G3_STR + k0) * 4);
                bl[2 * p][0] = r0;  bl[2 * p][1] = r1;
                bl[2 * p + 1][0] = r2;  bl[2 * p + 1][1] = r3;
            }
#pragma unroll
            for (int nt = 0; nt < 4; nt++) {
                mma_tf32(acc[nt], ah, bh[nt]);
                mma_tf32(acc[nt], ah, bl[nt]);
                mma_tf32(acc[nt], al, bh[nt]);
            }
        }
    }

#pragma unroll
    for (int nt = 0; nt < 4; nt++) {
        int col = wc * 32 + nt * 8 + 2 * qc;
#pragma unroll
        for (int h2 = 0; h2 < 2; h2++) {
            int row = m0 + wr * 16 + qr + 8 * h2;
            float2 o = make_float2(acc[nt][2 * h2], acc[nt][2 * h2 + 1]);
            *(float2*)(C + (size_t)row * MDIM + col) = o;
        }
    }
}

// =======================================================================
// One-shot tf32 GEMM for K=128 (steps 2 & 5)  (unchanged from R14)
// =======================================================================
#define EPI_SILU 1
#define EPI_RES  2
#define GT_SMEM  ((64 + 128) * 132 * 4)    // 101376 B

template <int EPI, bool CVTA>
__global__ __launch_bounds__(256, 2)
void gemm_tf32_k128(const float* __restrict__ A, const float* __restrict__ B,
                    const float* __restrict__ bias, const float* __restrict__ X,
                    float* __restrict__ C, int N)
{
    extern __shared__ float sm[];
    float* sA = sm;                  // [64][132]
    float* sB = sm + 64 * 132;       // [128][132]
    const uint32_t sA_u = smem_u32(sA);
    const uint32_t sB_u = smem_u32(sB);

    const int tid  = threadIdx.x;
    const int wid  = tid >> 5;
    const int lane = tid & 31;
    const int wr   = wid >> 2;
    const int wc   = wid & 3;
    const int qr   = lane >> 2;
    const int qc   = lane & 3;
    const int m0   = blockIdx.x * 64;
    const int n0   = blockIdx.y * 128;

    const int lt = lane >> 3;
    const int lr = lane & 7;
    const int a_off = (wr * 32 + (lt & 1) * 8 + lr) * 132 + (lt >> 1) * 4;
    const int b_off = (wc * 32 + (lt >> 1) * 8 + lr) * 132 + (lt & 1) * 4;

#pragma unroll
    for (int o = 0; o < 8; o++) {
        int li = o * 256 + tid;
        int row = li >> 5, g = li & 31;
        cp_async16(sA_u + (row * 132 + g * 4) * 4,
                   A + (size_t)(m0 + row) * MDIM + g * 4);
    }
#pragma unroll
    for (int o = 0; o < 16; o++) {
        int li = o * 256 + tid;
        int row = li >> 5, g = li & 31;
        cp_async16(sB_u + (row * 132 + g * 4) * 4,
                   B + (size_t)(n0 + row) * MDIM + g * 4);
    }
    cp_commit();

    float acc[2][4][4];
#pragma unroll
    for (int mt = 0; mt < 2; mt++)
#pragma unroll
        for (int nt = 0; nt < 4; nt++)
#pragma unroll
            for (int v = 0; v < 4; v++) acc[mt][nt][v] = 0.f;

    cp_wait<0>();
    __syncthreads();

#pragma unroll
    for (int k8 = 0; k8 < 16; k8++) {
        const int k0 = k8 * 8;
        uint32_t af[2][4], bf[4][2];
        if (CVTA) {
#pragma unroll
            for (int mt = 0; mt < 2; mt++) {
                const float* ar = sA + (wr * 32 + mt * 16 + qr) * 132 + k0 + qc;
                af[mt][0] = f2tf32(ar[0]);
                af[mt][1] = f2tf32(ar[8 * 132]);
                af[mt][2] = f2tf32(ar[4]);
                af[mt][3] = f2tf32(ar[8 * 132 + 4]);
            }
        } else {
#pragma unroll
            for (int mt = 0; mt < 2; mt++)
                ldsm_x4(af[mt][0], af[mt][1], af[mt][2], af[mt][3],
                        sA_u + (uint32_t)(a_off + mt * 16 * 132 + k0) * 4);
        }
#pragma unroll
        for (int p = 0; p < 2; p++) {
            uint32_t r0, r1, r2, r3;
            ldsm_x4(r0, r1, r2, r3,
                    sB_u + (uint32_t)(b_off + p * 16 * 132 + k0) * 4);
            bf[2 * p][0] = r0;  bf[2 * p][1] = r1;
            bf[2 * p + 1][0] = r2;  bf[2 * p + 1][1] = r3;
        }
#pragma unroll
        for (int mt = 0; mt < 2; mt++)
#pragma unroll
            for (int nt = 0; nt < 4; nt++)
                mma_tf32(acc[mt][nt], af[mt], bf[nt]);
    }

#pragma unroll
    for (int mt = 0; mt < 2; mt++) {
#pragma unroll
        for (int nt = 0; nt < 4; nt++) {
            int col = n0 + wc * 32 + nt * 8 + 2 * qc;
#pragma unroll
            for (int h2 = 0; h2 < 2; h2++) {
                int row = m0 + wr * 32 + mt * 16 + qr + 8 * h2;
                float v0 = acc[mt][nt][2 * h2];
                float v1 = acc[mt][nt][2 * h2 + 1];
                size_t base = (size_t)row * N + col;
                float2 o;
                if (EPI == EPI_SILU) {
                    float z0 = v0 + bias[col];
                    float z1 = v1 + bias[col + 1];
                    o.x = __uint_as_float(f2tf32(z0 / (1.f + expf(-z0))));
                    o.y = __uint_as_float(f2tf32(z1 / (1.f + expf(-z1))));
                } else {
                    float2 xv = *(const float2*)(X + base);
                    o.x = v0 + xv.x;
                    o.y = v1 + xv.y;
                }
                *(float2*)(C + base) = o;
            }
        }
    }
}

// =======================================================================
// K3, 2 CTAs/SM (unchanged from R13 — measured ~713 us)
// =======================================================================
#define K3_BM   128
#define K3_BN   128
#define K3_KC   32
#define K3_NCH  16                         // 512 / 32
#define K3_STR  36
#define K3_ASTG (K3_BM * K3_STR)           // 4608 floats
#define K3_BSTG (K3_BN * K3_STR)           // 4608 floats
#define K3_SMEM_BYTES (2 * (K3_ASTG + K3_BSTG) * 4)   // 73728 B

__global__ __launch_bounds__(256, 2)
void k3_mma(const float* __restrict__ W2r,
            const float* __restrict__ feats,
            const float* __restrict__ h,
            const float* __restrict__ b2,
            float* __restrict__ feats2)
{
    extern __shared__ float smf[];
    float* sAf = smf;                      // [2][4608]
    float* sBf = smf + 2 * K3_ASTG;        // [2][4608]
    const uint32_t sA_u = smem_u32(sAf);
    const uint32_t sB_u = smem_u32(sBf);

    const int tid  = threadIdx.x;
    const int wid  = tid >> 5;
    const int lane = tid & 31;
    const int wr   = wid >> 2;             // 0..1 -> rows 64*wr
    const int wc   = wid & 3;              // 0..3 -> j cols 32*wc
    const int qr   = lane >> 2;
    const int qc   = lane & 3;
    const int m0   = blockIdx.x * K3_BM;
    const int nb   = blockIdx.y;           // output column i

    const int lt = lane >> 3;
    const int lr = lane & 7;
    const int a_off = (wr * 64 + (lt & 1) * 8 + lr) * K3_STR + (lt >> 1) * 4;
    const int b_off = (wc * 32 + (lt >> 1) * 8 + lr) * K3_STR + (lt & 1) * 4;

    float acc[4][4][4];                    // 64 regs
#pragma unroll
    for (int mt = 0; mt < 4; mt++)
#pragma unroll
        for (int nt = 0; nt < 4; nt++)
#pragma unroll
            for (int v = 0; v < 4; v++) acc[mt][nt][v] = 0.f;

    auto load_chunk = [&](int c) {
        const int s = c & 1;
        const int kc = c * K3_KC;
        const uint32_t ab = sA_u + s * K3_ASTG * 4;
        const uint32_t bb = sB_u + s * K3_BSTG * 4;
#pragma unroll
        for (int o = 0; o < 4; o++) {
            int li = o * 256 + tid;
            int row = li >> 3, g = li & 7;
            cp_async16(ab + (row * K3_STR + g * 4) * 4,
                       h + (size_t)(m0 + row) * HDIM + kc + g * 4);
        }
#pragma unroll
        for (int o = 0; o < 4; o++) {
            int li = o * 256 + tid;
            int row = li >> 3, g = li & 7;
            cp_async16(bb + (row * K3_STR + g * 4) * 4,
                       W2r + (size_t)(nb * K3_BN + row) * HDIM + kc + g * 4);
        }
        cp_commit();
    };

    load_chunk(0);

    for (int c = 0; c < K3_NCH; c++) {
        cp_wait<0>();
        __syncthreads();
        if (c + 1 < K3_NCH) load_chunk(c + 1);

        const uint32_t ab = sA_u + (c & 1) * K3_ASTG * 4;
        const uint32_t bb = sB_u + (c & 1) * K3_BSTG * 4;

#pragma unroll
        for (int k8 = 0; k8 < 4; k8++) {
            const int k0 = k8 * 8;
            uint32_t af[4][4], bf[4][2];
#pragma unroll
            for (int mt = 0; mt < 4; mt++)
                ldsm_x4(af[mt][0], af[mt][1], af[mt][2], af[mt][3],
                        ab + (uint32_t)(a_off + mt * 16 * K3_STR + k0) * 4);
#pragma unroll
            for (int p = 0; p < 2; p++) {
                uint32_t r0, r1, r2, r3;
                ldsm_x4(r0, r1, r2, r3,
                        bb + (uint32_t)(b_off + p * 16 * K3_STR + k0) * 4);
                bf[2 * p][0] = r0;  bf[2 * p][1] = r1;
                bf[2 * p + 1][0] = r2;  bf[2 * p + 1][1] = r3;
            }
#pragma unroll
            for (int mt = 0; mt < 4; mt++)
#pragma unroll
                for (int nt = 0; nt < 4; nt++)
                    mma_tf32(acc[mt][nt], af[mt], bf[nt]);
        }
    }
    __syncthreads();   // all MMAs done before smem reuse below

    // ---- epilogue: stage feats [128][132] in smem, reduce over j ----
    float* fs   = smf;                          // 128*132 floats
    float* sRed = smf + 128 * 132;              // [128][4]
#pragma unroll
    for (int o = 0; o < 16; o++) {
        int li = o * 256 + tid;
        int row = li >> 5, g = li & 31;
        float4 v = *(const float4*)(feats + (size_t)(m0 + row) * MDIM + g * 4);
        float* d = fs + row * 132 + g * 4;
        d[0] = v.x; d[1] = v.y; d[2] = v.z; d[3] = v.w;
    }
    __syncthreads();

#pragma unroll
    for (int mt = 0; mt < 4; mt++) {
#pragma unroll
        for (int h2 = 0; h2 < 2; h2++) {
            int rl = wr * 64 + mt * 16 + qr + 8 * h2;
            float p = 0.f;
#pragma unroll
            for (int nt = 0; nt < 4; nt++) {
                int j0 = wc * 32 + nt * 8 + 2 * qc;
                p = fmaf(acc[mt][nt][2 * h2],     fs[rl * 132 + j0],     p);
                p = fmaf(acc[mt][nt][2 * h2 + 1], fs[rl * 132 + j0 + 1], p);
            }
            p += __shfl_xor_sync(0xffffffffu, p, 1);
            p += __shfl_xor_sync(0xffffffffu, p, 2);
            if (qc == 0) sRed[rl * 4 + wc] = p;
        }
    }
    __syncthreads();

    if (tid < 128) {
        int row = tid;
        float s = sRed[row * 4 + 0] + sRed[row * 4 + 1]
                + sRed[row * 4 + 2] + sRed[row * 4 + 3];
        // fold b2 bias term: + sum_j b2[nb*128 + j] * feats[row][j]
        const float4* bb2 = (const float4*)(b2 + (size_t)nb * MDIM);
        const float* fr = fs + row * 132;
        float bacc = 0.f;
#pragma unroll
        for (int j = 0; j < 32; j++) {
            float4 v = bb2[j];
            bacc = fmaf(v.x, fr[4 * j + 0],
                   fmaf(v.y, fr[4 * j + 1],
                   fmaf(v.z, fr[4 * j + 2],
                   fmaf(v.w, fr[4 * j + 3], bacc))));
        }
        feats2[(size_t)(m0 + row) * MDIM + nb] =
            __uint_as_float(f2tf32(s + bacc));
    }
}

// =======================================================================
// Host launcher
// =======================================================================
extern "C" void kernel_launch(void* const* d_in, const int* in_sizes, int n_in,
                              void* d_out, int out_size)
{
    const float* x    = (const float*)d_in[0];
    const float* Wmap = (const float*)d_in[1];
    const float* W1   = (const float*)d_in[2];
    const float* b1   = (const float*)d_in[3];
    const float* W2   = (const float*)d_in[4];
    const float* b2   = (const float*)d_in[5];
    float* out = (float*)d_out;

    void *pf, *ph, *pf2, *pwt, *pw2, *pw1, *pwh, *pwl;
    cudaGetSymbolAddress(&pf,  g_feats);
    cudaGetSymbolAddress(&ph,  g_h);
    cudaGetSymbolAddress(&pf2, g_feats2);
    cudaGetSymbolAddress(&pwt, g_wmapT);
    cudaGetSymbolAddress(&pw2, g_w2r);
    cudaGetSymbolAddress(&pw1, g_w1r);
    cudaGetSymbolAddress(&pwh, g_wmh);
    cudaGetSymbolAddress(&pwl, g_wml);
    float* feats  = (float*)pf;
    float* hbuf   = (float*)ph;
    float* feats2 = (float*)pf2;
    float* wmapT  = (float*)pwt;
    float* w2r    = (float*)pw2;
    float* w1r    = (float*)pw1;
    float* wmh    = (float*)pwh;
    float* wml    = (float*)pwl;

    cudaFuncSetAttribute(k3_mma, cudaFuncAttributeMaxDynamicSharedMemorySize,
                         K3_SMEM_BYTES);
    cudaFuncSetAttribute(gemm_3xtf32,
                         cudaFuncAttributeMaxDynamicSharedMemorySize, G3_SMEM);
    cudaFuncSetAttribute(gemm_tf32_k128<EPI_SILU, true>,
                         cudaFuncAttributeMaxDynamicSharedMemorySize, GT_SMEM);
    cudaFuncSetAttribute(gemm_tf32_k128<EPI_RES, false>,
                         cudaFuncAttributeMaxDynamicSharedMemorySize, GT_SMEM);

    dim3 blk(256);

    // 0a) pre-round W2, W1; split W_map into tf32 hi/lo
    round_tf32_kernel<<<2048, blk>>>((const float4*)W2, (float4*)w2r,
                                     MDIM * MDIM * HDIM / 4);
    round_tf32_kernel<<<64, blk>>>((const float4*)W1, (float4*)w1r,
                                   4 * MDIM * MDIM / 4);
    split_tf32_kernel<<<64, blk>>>((const float4*)Wmap, (float4*)wmh,
                                   (float4*)wml, MDIM * VDIM / 4);
    // 0b) WmapT = round(W_map^T)
    transpose_wmap<<<dim3(VDIM / 32, MDIM / 32), blk>>>(Wmap, wmapT);

    // 1) feats = x @ W_map^T  via 3xTF32, BM=32, 2 CTAs/SM
    gemm_3xtf32<<<NROWS / 32, blk, G3_SMEM>>>(x, wmh, wml, feats);

    // 2) h = round(silu(feats @ W1^T + b1))  (tf32, M64 tiles, 2 CTAs/SM)
    gemm_tf32_k128<EPI_SILU, true><<<dim3(NROWS / 64, HDIM / 128), blk, GT_SMEM>>>(
        feats, w1r, b1, nullptr, hbuf, HDIM);

    // 3+4) feats2 = round(((h @ W2r^T) + b2-term) . feats)  — 2 CTAs/SM
    k3_mma<<<dim3(NROWS / K3_BM, MDIM), blk, K3_SMEM_BYTES>>>(
        w2r, feats, hbuf, b2, feats2);

    // 5) out = x + feats2 @ wmapT^T   (tf32, M64 tiles, 2 CTAs/SM)
    gemm_tf32_k128<EPI_RES, false><<<dim3(NROWS / 64, VDIM / 128), blk, GT_SMEM>>>(
        feats2, wmapT, nullptr, x, out, VDIM);
}

// round 17
// speedup vs baseline: 1.0159x; 1.0159x over previous
#include <cuda_runtime.h>
#include <cstdint>
#include <cstdio>

// Problem dims (fixed)
#define NROWS 8192
#define VDIM  2048
#define MDIM  128
#define HDIM  512

// Scratch (allocation-free rule: __device__ globals)
__device__ __align__(256) float g_feats [NROWS * MDIM];     // 4 MB
__device__ __align__(256) float g_h     [NROWS * HDIM];     // 16 MB (tf32-rounded)
__device__ __align__(256) float g_feats2[NROWS * MDIM];     // 4 MB (tf32-rounded)
__device__ __align__(256) float g_wmapT [VDIM * MDIM];      // 1 MB (tf32-rounded)
__device__ __align__(256) float g_w2r   [MDIM * MDIM * HDIM]; // 64 MB (tf32 W2)
__device__ __align__(256) float g_w1r   [4 * MDIM * MDIM];  // 256 KB (tf32 W1)
__device__ __align__(256) float g_wmh   [MDIM * VDIM];      // 1 MB (Wmap hi)
__device__ __align__(256) float g_wml   [MDIM * VDIM];      // 1 MB (Wmap lo)

// ---------------- common PTX helpers ----------------
__device__ __forceinline__ uint32_t smem_u32(const void* p) {
    uint32_t a;
    asm("{ .reg .u64 t; cvta.to.shared.u64 t, %1; cvt.u32.u64 %0, t; }"
        : "=r"(a) : "l"(p));
    return a;
}
__device__ __forceinline__ void cp_async16(uint32_t dst, const void* src) {
    asm volatile("cp.async.cg.shared.global [%0], [%1], 16;"
                 :: "r"(dst), "l"(src));
}
__device__ __forceinline__ void cp_commit() {
    asm volatile("cp.async.commit_group;" ::: "memory");
}
template <int N>
__device__ __forceinline__ void cp_wait() {
    asm volatile("cp.async.wait_group %0;" :: "n"(N) : "memory");
}
__device__ __forceinline__ uint32_t f2tf32(float f) {
    uint32_t r;
    asm("cvt.rna.tf32.f32 %0, %1;" : "=r"(r) : "f"(f));
    return r;
}
__device__ __forceinline__ void mma_tf32(float* d, const uint32_t* a,
                                         const uint32_t* b) {
    asm volatile(
        "mma.sync.aligned.m16n8k8.row.col.f32.tf32.tf32.f32 "
        "{%0,%1,%2,%3}, {%4,%5,%6,%7}, {%8,%9}, {%0,%1,%2,%3};"
        : "+f"(d[0]), "+f"(d[1]), "+f"(d[2]), "+f"(d[3])
        : "r"(a[0]), "r"(a[1]), "r"(a[2]), "r"(a[3]), "r"(b[0]), "r"(b[1]));
}
__device__ __forceinline__ void ldsm_x4(uint32_t& r0, uint32_t& r1,
                                        uint32_t& r2, uint32_t& r3,
                                        uint32_t addr) {
    asm volatile("ldmatrix.sync.aligned.m8n8.x4.shared.b16 {%0,%1,%2,%3}, [%4];"
                 : "=r"(r0), "=r"(r1), "=r"(r2), "=r"(r3) : "r"(addr));
}

// =======================================================================
// FUSED pre-pass: one launch does all four independent prep tasks.
//   blocks [0,2048)      : w2r  = round(W2)         (16.78M elems)
//   blocks [2048,2112)   : w1r  = round(W1)         (256K elems)
//   blocks [2112,2176)   : wmh/wml = split(Wmap)    (256K elems)
//   blocks [2176,2432)   : wmapT = round(Wmap^T)    (256K elems)
// Tiny tasks ride concurrently under W2's ~22us memory floor.
// =======================================================================
#define PRE_BLOCKS 2432

__global__ __launch_bounds__(256)
void prepass_kernel(const float4* __restrict__ W2, float4* __restrict__ w2r,
                    const float4* __restrict__ W1, float4* __restrict__ w1r,
                    const float4* __restrict__ Wm4,
                    float4* __restrict__ wmh, float4* __restrict__ wml,
                    const float* __restrict__ Wm, float* __restrict__ WT)
{
    __shared__ float t[32][33];
    const int b = blockIdx.x;
    const int tid = threadIdx.x;

    if (b < 2048) {
        // ---- round W2 ----
        const int n4 = MDIM * MDIM * HDIM / 4;
        for (int i = b * 256 + tid; i < n4; i += 2048 * 256) {
            float4 v = W2[i];
            float4 o;
            o.x = __uint_as_float(f2tf32(v.x));
            o.y = __uint_as_float(f2tf32(v.y));
            o.z = __uint_as_float(f2tf32(v.z));
            o.w = __uint_as_float(f2tf32(v.w));
            w2r[i] = o;
        }
    } else if (b < 2112) {
        // ---- round W1 (16384 float4, exactly 64 blocks x 256) ----
        int i = (b - 2048) * 256 + tid;
        float4 v = W1[i];
        float4 o;
        o.x = __uint_as_float(f2tf32(v.x));
        o.y = __uint_as_float(f2tf32(v.y));
        o.z = __uint_as_float(f2tf32(v.z));
        o.w = __uint_as_float(f2tf32(v.w));
        w1r[i] = o;
    } else if (b < 2176) {
        // ---- split Wmap (131072 float4, 64 blocks, 8 each) ----
        const int n4 = MDIM * VDIM / 4;
        for (int i = (b - 2112) * 256 + tid; i < n4; i += 64 * 256) {
            float4 v = Wm4[i];
            float4 h4, l4;
            h4.x = __uint_as_float(f2tf32(v.x)); l4.x = __uint_as_float(f2tf32(v.x - h4.x));
            h4.y = __uint_as_float(f2tf32(v.y)); l4.y = __uint_as_float(f2tf32(v.y - h4.y));
            h4.z = __uint_as_float(f2tf32(v.z)); l4.z = __uint_as_float(f2tf32(v.z - h4.z));
            h4.w = __uint_as_float(f2tf32(v.w)); l4.w = __uint_as_float(f2tf32(v.w - h4.w));
            wmh[i] = h4;
            wml[i] = l4;
        }
    } else {
        // ---- transpose + round Wmap: tile idx 0..255 -> (bx 0..63, by 0..3) ----
        const int idx = b - 2176;
        const int bx = (idx & 63) * 32;   // v
        const int by = (idx >> 6) * 32;   // i
        const int tx = tid & 31;
        const int ty = tid >> 5;          // 0..7
#pragma unroll
        for (int r = 0; r < 32; r += 8)
            t[ty + r][tx] = Wm[(size_t)(by + ty + r) * VDIM + bx + tx];
        __syncthreads();
#pragma unroll
        for (int r = 0; r < 32; r += 8)
            WT[(size_t)(bx + ty + r) * MDIM + by + tx] =
                __uint_as_float(f2tf32(t[tx][ty + r]));
    }
}

// =======================================================================
// Step 1 via 3xTF32 with FUSED x split  (REVERTED to R15 shape — measured):
//   feats = x @ Wmap^T;  hi = rnd(x), lo = rnd(x - hi) in registers.
// Stage: x raw [0,64) rows, Bhi [64,192), Blo [192,320), stride 68.
// M-tile 64, KC=64, 2-stage cp.async ring, ldmatrix. 1 CTA/SM, grid 128.
// =======================================================================
#define G3_KC    64
#define G3_NCH   (VDIM / G3_KC)            // 32
#define G3_STR   68
#define G3_STAGE (320 * G3_STR)            // 21760 floats
#define G3_SMEM  (2 * G3_STAGE * 4)        // 174080 B

__global__ __launch_bounds__(256, 1)
void gemm_3xtf32(const float* __restrict__ x,
                 const float* __restrict__ wmh, const float* __restrict__ wml,
                 float* __restrict__ C)
{
    extern __shared__ float smf[];
    const uint32_t s_u = smem_u32(smf);

    const int tid  = threadIdx.x;
    const int wid  = tid >> 5;
    const int lane = tid & 31;
    const int wr   = wid >> 2;
    const int wc   = wid & 3;
    const int qr   = lane >> 2;
    const int qc   = lane & 3;
    const int m0   = blockIdx.x * 64;

    const int lt = lane >> 3;
    const int lr = lane & 7;
    const int a_off = (wr * 32 + (lt & 1) * 8 + lr) * G3_STR + (lt >> 1) * 4;
    const int b_off = (wc * 32 + (lt >> 1) * 8 + lr) * G3_STR + (lt & 1) * 4;

    float acc[2][4][4];
#pragma unroll
    for (int mt = 0; mt < 2; mt++)
#pragma unroll
        for (int nt = 0; nt < 4; nt++)
#pragma unroll
            for (int v = 0; v < 4; v++) acc[mt][nt][v] = 0.f;

    auto load_chunk = [&](int c) {
        const int s = c & 1;
        const int kc = c * G3_KC;
        const uint32_t base = s_u + s * G3_STAGE * 4;
#pragma unroll
        for (int o = 0; o < 4; o++) {       // x raw: 64 rows x 16 granules
            int li = o * 256 + tid;
            int row = li >> 4, g = li & 15;
            cp_async16(base + (row * G3_STR + g * 4) * 4,
                       x + (size_t)(m0 + row) * VDIM + kc + g * 4);
        }
#pragma unroll
        for (int o = 0; o < 8; o++) {       // B hi: 128 rows x 16 granules
            int li = o * 256 + tid;
            int row = li >> 4, g = li & 15;
            cp_async16(base + ((64 + row) * G3_STR + g * 4) * 4,
                       wmh + (size_t)row * VDIM + kc + g * 4);
        }
#pragma unroll
        for (int o = 0; o < 8; o++) {       // B lo
            int li = o * 256 + tid;
            int row = li >> 4, g = li & 15;
            cp_async16(base + ((192 + row) * G3_STR + g * 4) * 4,
                       wml + (size_t)row * VDIM + kc + g * 4);
        }
        cp_commit();
    };

    load_chunk(0);

    for (int c = 0; c < G3_NCH; c++) {
        cp_wait<0>();
        __syncthreads();
        if (c + 1 < G3_NCH) load_chunk(c + 1);

        const uint32_t base = s_u + (c & 1) * G3_STAGE * 4;
        const uint32_t axo = base + (uint32_t)a_off * 4;
        const uint32_t bho = base + 64u * G3_STR * 4 + (uint32_t)b_off * 4;
        const uint32_t blo_ = base + 192u * G3_STR * 4 + (uint32_t)b_off * 4;

#pragma unroll
        for (int k8 = 0; k8 < 8; k8++) {
            const int k0 = k8 * 8;
            uint32_t ah[2][4], al[2][4], bh[4][2], bl[4][2];
#pragma unroll
            for (int mt = 0; mt < 2; mt++) {
                uint32_t ar[4];
                ldsm_x4(ar[0], ar[1], ar[2], ar[3],
                        axo + (uint32_t)(mt * 16 * G3_STR + k0) * 4);
#pragma unroll
                for (int e = 0; e < 4; e++) {
                    float f  = __uint_as_float(ar[e]);
                    uint32_t hb = f2tf32(f);
                    ah[mt][e] = hb;
                    al[mt][e] = f2tf32(f - __uint_as_float(hb));
                }
            }
#pragma unroll
            for (int p = 0; p < 2; p++) {
                uint32_t r0, r1, r2, r3;
                ldsm_x4(r0, r1, r2, r3,
                        bho + (uint32_t)(p * 16 * G3_STR + k0) * 4);
                bh[2 * p][0] = r0;  bh[2 * p][1] = r1;
                bh[2 * p + 1][0] = r2;  bh[2 * p + 1][1] = r3;
                ldsm_x4(r0, r1, r2, r3,
                        blo_ + (uint32_t)(p * 16 * G3_STR + k0) * 4);
                bl[2 * p][0] = r0;  bl[2 * p][1] = r1;
                bl[2 * p + 1][0] = r2;  bl[2 * p + 1][1] = r3;
            }
#pragma unroll
            for (int mt = 0; mt < 2; mt++)
#pragma unroll
                for (int nt = 0; nt < 4; nt++) {
                    mma_tf32(acc[mt][nt], ah[mt], bh[nt]);
                    mma_tf32(acc[mt][nt], ah[mt], bl[nt]);
                    mma_tf32(acc[mt][nt], al[mt], bh[nt]);
                }
        }
    }

#pragma unroll
    for (int mt = 0; mt < 2; mt++) {
#pragma unroll
        for (int nt = 0; nt < 4; nt++) {
            int col = wc * 32 + nt * 8 + 2 * qc;
#pragma unroll
            for (int h2 = 0; h2 < 2; h2++) {
                int row = m0 + wr * 32 + mt * 16 + qr + 8 * h2;
                float2 o = make_float2(acc[mt][nt][2 * h2],
                                       acc[mt][nt][2 * h2 + 1]);
                *(float2*)(C + (size_t)row * MDIM + col) = o;
            }
        }
    }
}

// =======================================================================
// One-shot tf32 GEMM for K=128 (steps 2 & 5)  (unchanged from R14)
// =======================================================================
#define EPI_SILU 1
#define EPI_RES  2
#define GT_SMEM  ((64 + 128) * 132 * 4)    // 101376 B

template <int EPI, bool CVTA>
__global__ __launch_bounds__(256, 2)
void gemm_tf32_k128(const float* __restrict__ A, const float* __restrict__ B,
                    const float* __restrict__ bias, const float* __restrict__ X,
                    float* __restrict__ C, int N)
{
    extern __shared__ float sm[];
    float* sA = sm;                  // [64][132]
    float* sB = sm + 64 * 132;       // [128][132]
    const uint32_t sA_u = smem_u32(sA);
    const uint32_t sB_u = smem_u32(sB);

    const int tid  = threadIdx.x;
    const int wid  = tid >> 5;
    const int lane = tid & 31;
    const int wr   = wid >> 2;
    const int wc   = wid & 3;
    const int qr   = lane >> 2;
    const int qc   = lane & 3;
    const int m0   = blockIdx.x * 64;
    const int n0   = blockIdx.y * 128;

    const int lt = lane >> 3;
    const int lr = lane & 7;
    const int a_off = (wr * 32 + (lt & 1) * 8 + lr) * 132 + (lt >> 1) * 4;
    const int b_off = (wc * 32 + (lt >> 1) * 8 + lr) * 132 + (lt & 1) * 4;

#pragma unroll
    for (int o = 0; o < 8; o++) {
        int li = o * 256 + tid;
        int row = li >> 5, g = li & 31;
        cp_async16(sA_u + (row * 132 + g * 4) * 4,
                   A + (size_t)(m0 + row) * MDIM + g * 4);
    }
#pragma unroll
    for (int o = 0; o < 16; o++) {
        int li = o * 256 + tid;
        int row = li >> 5, g = li & 31;
        cp_async16(sB_u + (row * 132 + g * 4) * 4,
                   B + (size_t)(n0 + row) * MDIM + g * 4);
    }
    cp_commit();

    float acc[2][4][4];
#pragma unroll
    for (int mt = 0; mt < 2; mt++)
#pragma unroll
        for (int nt = 0; nt < 4; nt++)
#pragma unroll
            for (int v = 0; v < 4; v++) acc[mt][nt][v] = 0.f;

    cp_wait<0>();
    __syncthreads();

#pragma unroll
    for (int k8 = 0; k8 < 16; k8++) {
        const int k0 = k8 * 8;
        uint32_t af[2][4], bf[4][2];
        if (CVTA) {
#pragma unroll
            for (int mt = 0; mt < 2; mt++) {
                const float* ar = sA + (wr * 32 + mt * 16 + qr) * 132 + k0 + qc;
                af[mt][0] = f2tf32(ar[0]);
                af[mt][1] = f2tf32(ar[8 * 132]);
                af[mt][2] = f2tf32(ar[4]);
                af[mt][3] = f2tf32(ar[8 * 132 + 4]);
            }
        } else {
#pragma unroll
            for (int mt = 0; mt < 2; mt++)
                ldsm_x4(af[mt][0], af[mt][1], af[mt][2], af[mt][3],
                        sA_u + (uint32_t)(a_off + mt * 16 * 132 + k0) * 4);
        }
#pragma unroll
        for (int p = 0; p < 2; p++) {
            uint32_t r0, r1, r2, r3;
            ldsm_x4(r0, r1, r2, r3,
                    sB_u + (uint32_t)(b_off + p * 16 * 132 + k0) * 4);
            bf[2 * p][0] = r0;  bf[2 * p][1] = r1;
            bf[2 * p + 1][0] = r2;  bf[2 * p + 1][1] = r3;
        }
#pragma unroll
        for (int mt = 0; mt < 2; mt++)
#pragma unroll
            for (int nt = 0; nt < 4; nt++)
                mma_tf32(acc[mt][nt], af[mt], bf[nt]);
    }

#pragma unroll
    for (int mt = 0; mt < 2; mt++) {
#pragma unroll
        for (int nt = 0; nt < 4; nt++) {
            int col = n0 + wc * 32 + nt * 8 + 2 * qc;
#pragma unroll
            for (int h2 = 0; h2 < 2; h2++) {
                int row = m0 + wr * 32 + mt * 16 + qr + 8 * h2;
                float v0 = acc[mt][nt][2 * h2];
                float v1 = acc[mt][nt][2 * h2 + 1];
                size_t base = (size_t)row * N + col;
                float2 o;
                if (EPI == EPI_SILU) {
                    float z0 = v0 + bias[col];
                    float z1 = v1 + bias[col + 1];
                    o.x = __uint_as_float(f2tf32(z0 / (1.f + expf(-z0))));
                    o.y = __uint_as_float(f2tf32(z1 / (1.f + expf(-z1))));
                } else {
                    float2 xv = *(const float2*)(X + base);
                    o.x = v0 + xv.x;
                    o.y = v1 + xv.y;
                }
                *(float2*)(C + base) = o;
            }
        }
    }
}

// =======================================================================
// K3, 2 CTAs/SM (unchanged from R13 — measured ~713 us)
// =======================================================================
#define K3_BM   128
#define K3_BN   128
#define K3_KC   32
#define K3_NCH  16                         // 512 / 32
#define K3_STR  36
#define K3_ASTG (K3_BM * K3_STR)           // 4608 floats
#define K3_BSTG (K3_BN * K3_STR)           // 4608 floats
#define K3_SMEM_BYTES (2 * (K3_ASTG + K3_BSTG) * 4)   // 73728 B

__global__ __launch_bounds__(256, 2)
void k3_mma(const float* __restrict__ W2r,
            const float* __restrict__ feats,
            const float* __restrict__ h,
            const float* __restrict__ b2,
            float* __restrict__ feats2)
{
    extern __shared__ float smf[];
    float* sAf = smf;                      // [2][4608]
    float* sBf = smf + 2 * K3_ASTG;        // [2][4608]
    const uint32_t sA_u = smem_u32(sAf);
    const uint32_t sB_u = smem_u32(sBf);

    const int tid  = threadIdx.x;
    const int wid  = tid >> 5;
    const int lane = tid & 31;
    const int wr   = wid >> 2;             // 0..1 -> rows 64*wr
    const int wc   = wid & 3;              // 0..3 -> j cols 32*wc
    const int qr   = lane >> 2;
    const int qc   = lane & 3;
    const int m0   = blockIdx.x * K3_BM;
    const int nb   = blockIdx.y;           // output column i

    const int lt = lane >> 3;
    const int lr = lane & 7;
    const int a_off = (wr * 64 + (lt & 1) * 8 + lr) * K3_STR + (lt >> 1) * 4;
    const int b_off = (wc * 32 + (lt >> 1) * 8 + lr) * K3_STR + (lt & 1) * 4;

    float acc[4][4][4];                    // 64 regs
#pragma unroll
    for (int mt = 0; mt < 4; mt++)
#pragma unroll
        for (int nt = 0; nt < 4; nt++)
#pragma unroll
            for (int v = 0; v < 4; v++) acc[mt][nt][v] = 0.f;

    auto load_chunk = [&](int c) {
        const int s = c & 1;
        const int kc = c * K3_KC;
        const uint32_t ab = sA_u + s * K3_ASTG * 4;
        const uint32_t bb = sB_u + s * K3_BSTG * 4;
#pragma unroll
        for (int o = 0; o < 4; o++) {
            int li = o * 256 + tid;
            int row = li >> 3, g = li & 7;
            cp_async16(ab + (row * K3_STR + g * 4) * 4,
                       h + (size_t)(m0 + row) * HDIM + kc + g * 4);
        }
#pragma unroll
        for (int o = 0; o < 4; o++) {
            int li = o * 256 + tid;
            int row = li >> 3, g = li & 7;
            cp_async16(bb + (row * K3_STR + g * 4) * 4,
                       W2r + (size_t)(nb * K3_BN + row) * HDIM + kc + g * 4);
        }
        cp_commit();
    };

    load_chunk(0);

    for (int c = 0; c < K3_NCH; c++) {
        cp_wait<0>();
        __syncthreads();
        if (c + 1 < K3_NCH) load_chunk(c + 1);

        const uint32_t ab = sA_u + (c & 1) * K3_ASTG * 4;
        const uint32_t bb = sB_u + (c & 1) * K3_BSTG * 4;

#pragma unroll
        for (int k8 = 0; k8 < 4; k8++) {
            const int k0 = k8 * 8;
            uint32_t af[4][4], bf[4][2];
#pragma unroll
            for (int mt = 0; mt < 4; mt++)
                ldsm_x4(af[mt][0], af[mt][1], af[mt][2], af[mt][3],
                        ab + (uint32_t)(a_off + mt * 16 * K3_STR + k0) * 4);
#pragma unroll
            for (int p = 0; p < 2; p++) {
                uint32_t r0, r1, r2, r3;
                ldsm_x4(r0, r1, r2, r3,
                        bb + (uint32_t)(b_off + p * 16 * K3_STR + k0) * 4);
                bf[2 * p][0] = r0;  bf[2 * p][1] = r1;
                bf[2 * p + 1][0] = r2;  bf[2 * p + 1][1] = r3;
            }
#pragma unroll
            for (int mt = 0; mt < 4; mt++)
#pragma unroll
                for (int nt = 0; nt < 4; nt++)
                    mma_tf32(acc[mt][nt], af[mt], bf[nt]);
        }
    }
    __syncthreads();   // all MMAs done before smem reuse below

    // ---- epilogue: stage feats [128][132] in smem, reduce over j ----
    float* fs   = smf;                          // 128*132 floats
    float* sRed = smf + 128 * 132;              // [128][4]
#pragma unroll
    for (int o = 0; o < 16; o++) {
        int li = o * 256 + tid;
        int row = li >> 5, g = li & 31;
        float4 v = *(const float4*)(feats + (size_t)(m0 + row) * MDIM + g * 4);
        float* d = fs + row * 132 + g * 4;
        d[0] = v.x; d[1] = v.y; d[2] = v.z; d[3] = v.w;
    }
    __syncthreads();

#pragma unroll
    for (int mt = 0; mt < 4; mt++) {
#pragma unroll
        for (int h2 = 0; h2 < 2; h2++) {
            int rl = wr * 64 + mt * 16 + qr + 8 * h2;
            float p = 0.f;
#pragma unroll
            for (int nt = 0; nt < 4; nt++) {
                int j0 = wc * 32 + nt * 8 + 2 * qc;
                p = fmaf(acc[mt][nt][2 * h2],     fs[rl * 132 + j0],     p);
                p = fmaf(acc[mt][nt][2 * h2 + 1], fs[rl * 132 + j0 + 1], p);
            }
            p += __shfl_xor_sync(0xffffffffu, p, 1);
            p += __shfl_xor_sync(0xffffffffu, p, 2);
            if (qc == 0) sRed[rl * 4 + wc] = p;
        }
    }
    __syncthreads();

    if (tid < 128) {
        int row = tid;
        float s = sRed[row * 4 + 0] + sRed[row * 4 + 1]
                + sRed[row * 4 + 2] + sRed[row * 4 + 3];
        // fold b2 bias term: + sum_j b2[nb*128 + j] * feats[row][j]
        const float4* bb2 = (const float4*)(b2 + (size_t)nb * MDIM);
        const float* fr = fs + row * 132;
        float bacc = 0.f;
#pragma unroll
        for (int j = 0; j < 32; j++) {
            float4 v = bb2[j];
            bacc = fmaf(v.x, fr[4 * j + 0],
                   fmaf(v.y, fr[4 * j + 1],
                   fmaf(v.z, fr[4 * j + 2],
                   fmaf(v.w, fr[4 * j + 3], bacc))));
        }
        feats2[(size_t)(m0 + row) * MDIM + nb] =
            __uint_as_float(f2tf32(s + bacc));
    }
}

// =======================================================================
// Host launcher
// =======================================================================
extern "C" void kernel_launch(void* const* d_in, const int* in_sizes, int n_in,
                              void* d_out, int out_size)
{
    const float* x    = (const float*)d_in[0];
    const float* Wmap = (const float*)d_in[1];
    const float* W1   = (const float*)d_in[2];
    const float* b1   = (const float*)d_in[3];
    const float* W2   = (const float*)d_in[4];
    const float* b2   = (const float*)d_in[5];
    float* out = (float*)d_out;

    void *pf, *ph, *pf2, *pwt, *pw2, *pw1, *pwh, *pwl;
    cudaGetSymbolAddress(&pf,  g_feats);
    cudaGetSymbolAddress(&ph,  g_h);
    cudaGetSymbolAddress(&pf2, g_feats2);
    cudaGetSymbolAddress(&pwt, g_wmapT);
    cudaGetSymbolAddress(&pw2, g_w2r);
    cudaGetSymbolAddress(&pw1, g_w1r);
    cudaGetSymbolAddress(&pwh, g_wmh);
    cudaGetSymbolAddress(&pwl, g_wml);
    float* feats  = (float*)pf;
    float* hbuf   = (float*)ph;
    float* feats2 = (float*)pf2;
    float* wmapT  = (float*)pwt;
    float* w2r    = (float*)pw2;
    float* w1r    = (float*)pw1;
    float* wmh    = (float*)pwh;
    float* wml    = (float*)pwl;

    cudaFuncSetAttribute(k3_mma, cudaFuncAttributeMaxDynamicSharedMemorySize,
                         K3_SMEM_BYTES);
    cudaFuncSetAttribute(gemm_3xtf32,
                         cudaFuncAttributeMaxDynamicSharedMemorySize, G3_SMEM);
    cudaFuncSetAttribute(gemm_tf32_k128<EPI_SILU, true>,
                         cudaFuncAttributeMaxDynamicSharedMemorySize, GT_SMEM);
    cudaFuncSetAttribute(gemm_tf32_k128<EPI_RES, false>,
                         cudaFuncAttributeMaxDynamicSharedMemorySize, GT_SMEM);

    dim3 blk(256);

    // 0) fused pre-pass: round W2/W1, split Wmap, transpose Wmap — ONE launch
    prepass_kernel<<<PRE_BLOCKS, blk>>>(
        (const float4*)W2, (float4*)w2r,
        (const float4*)W1, (float4*)w1r,
        (const float4*)Wmap, (float4*)wmh, (float4*)wml,
        Wmap, wmapT);

    // 1) feats = x @ W_map^T  via 3xTF32 with in-register x split (R15 shape)
    gemm_3xtf32<<<NROWS / 64, blk, G3_SMEM>>>(x, wmh, wml, feats);

    // 2) h = round(silu(feats @ W1^T + b1))  (tf32, M64 tiles, 2 CTAs/SM)
    gemm_tf32_k128<EPI_SILU, true><<<dim3(NROWS / 64, HDIM / 128), blk, GT_SMEM>>>(
        feats, w1r, b1, nullptr, hbuf, HDIM);

    // 3+4) feats2 = round(((h @ W2r^T) + b2-term) . feats)  — 2 CTAs/SM
    k3_mma<<<dim3(NROWS / K3_BM, MDIM), blk, K3_SMEM_BYTES>>>(
        w2r, feats, hbuf, b2, feats2);

    // 5) out = x + feats2 @ wmapT^T   (tf32, M64 tiles, 2 CTAs/SM)
    gemm_tf32_k128<EPI_RES, false><<<dim3(NROWS / 64, VDIM / 128), blk, GT_SMEM>>>(
        feats2, wmapT, nullptr, x, out, VDIM);
}